// round 14
// baseline (speedup 1.0000x reference)
#include <cuda_runtime.h>
#include <math.h>

#define N 4096
#define NTHREADS 1024
#define NCTA_ROW 64
#define SLICE 64
#define CHUNK 4          // per-thread chunk for PAV stage (a)

typedef unsigned long long u64;
typedef unsigned int u32;

__device__ u64   g_keys[2][N];
__device__ float g_rank[2][N];
__device__ float g_sum[2], g_sumsq[2], g_bce2[2];
__device__ u32   g_tick[2][N];     // tie tickets (reset by finisher each launch)
__device__ u32   g_cnt[2];
__device__ u32   g_cnt2;

// ---- float -> order-preserving uint (ascending), exact inverse ----
__device__ __forceinline__ u32 encodeVal(float v) {
    u32 b = __float_as_uint(v);
    return (b & 0x80000000u) ? ~b : (b | 0x80000000u);
}
__device__ __forceinline__ float decodeVal(u32 e) {
    return (e & 0x80000000u) ? __uint_as_float(e ^ 0x80000000u)
                             : __uint_as_float(~e);
}

// predicated accumulate, guaranteed 2-instr forms on separate pipes
__device__ __forceinline__ void cmpAccF(float& cf, float a, float vi) {
    asm("{.reg .pred p; setp.gt.f32 p, %1, %2;\n\t"
        "@p add.f32 %0, %0, 0f3F800000;}\n"
        : "+f"(cf) : "f"(a), "f"(vi));
}
__device__ __forceinline__ void cmpAccU(u32& c, u32 a, u32 ei) {
    asm("{.reg .pred p; setp.gt.u32 p, %1, %2;\n\t"
        "@p add.u32 %0, %0, 1;}\n"
        : "+r"(c) : "r"(a), "r"(ei));
}

__device__ __forceinline__ uint4 packAtom(float S, float W, float C, int st) {
    uint4 a;
    a.x = __float_as_uint(S); a.y = __float_as_uint(W);
    a.z = __float_as_uint(C); a.w = (u32)st;
    return a;
}

// Serially merge nLists PAV block-lists (atoms in stream order) onto D.
// Identical pooling arithmetic as the serial PAV stream -> identical result.
__device__ __forceinline__ int mergeLists(const uint4* srcBase, int stride,
                                          const int* cnts, int first, int nLists,
                                          uint4* D) {
    float tS = 0.f, tW = 0.f, tC = 0.f, tNum = 0.f;
    int   tSt = 0, sp = 0;
    bool init = false;
    for (int L = 0; L < nLists; L++) {
        const uint4* src = srcBase + (first + L) * stride;
        int c = cnts[first + L];
        for (int r = 0; r < c; r++) {
            uint4 b = src[r];
            float cS = __uint_as_float(b.x), cW = __uint_as_float(b.y);
            float cC = __uint_as_float(b.z);
            int   cSt = (int)b.w;
            float cNum = cS - cW;
            if (!init) { tS = cS; tW = cW; tC = cC; tSt = cSt; tNum = cNum; init = true; continue; }
            while (tNum * cC < cNum * tC) {      // pool
                cS += tS; cW += tW; cC += tC; cSt = tSt;
                cNum = cS - cW;
                if (sp == 0) { tC = 0.f; break; }
                sp--;
                uint4 p = D[sp];
                tS = __uint_as_float(p.x); tW = __uint_as_float(p.y);
                tC = __uint_as_float(p.z); tSt = (int)p.w;
                tNum = tS - tW;
            }
            if (tC > 0.f) D[sp++] = packAtom(tS, tW, tC, tSt);
            tS = cS; tW = cW; tC = cC; tSt = cSt; tNum = cNum;
        }
    }
    D[sp++] = packAtom(tS, tW, tC, tSt);
    return sp;
}

__device__ __forceinline__ float blockReduceSum(float v, float* scratch) {
#pragma unroll
    for (int o = 16; o; o >>= 1) v += __shfl_down_sync(0xffffffffu, v, o);
    int w = threadIdx.x >> 5, l = threadIdx.x & 31;
    __syncthreads();
    if (l == 0) scratch[w] = v;
    __syncthreads();
    if (w == 0) {
        float t = scratch[l];   // exactly 32 warps
#pragma unroll
        for (int o = 16; o; o >>= 1) t += __shfl_down_sync(0xffffffffu, t, o);
        if (l == 0) scratch[0] = t;
    }
    __syncthreads();
    return scratch[0];
}

// fused 3-way block reduction: one scratch round instead of three
__device__ __forceinline__ void blockReduce3(float& a, float& b, float& c,
                                             float* scratch) {
#pragma unroll
    for (int o = 16; o; o >>= 1) {
        a += __shfl_down_sync(0xffffffffu, a, o);
        b += __shfl_down_sync(0xffffffffu, b, o);
        c += __shfl_down_sync(0xffffffffu, c, o);
    }
    int w = threadIdx.x >> 5, l = threadIdx.x & 31;
    __syncthreads();
    if (l == 0) { scratch[w] = a; scratch[32 + w] = b; scratch[64 + w] = c; }
    __syncthreads();
    if (w == 0) {
        float ta = scratch[l], tb = scratch[32 + l], tc = scratch[64 + l];
#pragma unroll
        for (int o = 16; o; o >>= 1) {
            ta += __shfl_down_sync(0xffffffffu, ta, o);
            tb += __shfl_down_sync(0xffffffffu, tb, o);
            tc += __shfl_down_sync(0xffffffffu, tc, o);
        }
        if (l == 0) { scratch[0] = ta; scratch[32] = tb; scratch[64] = tc; }
    }
    __syncthreads();
    a = scratch[0]; b = scratch[32]; c = scratch[64];
}

// ---- SMEM byte offsets ----
#define SM_KARR   0        // u64[4096] 32768   | counting: fArr f32[4096] (16KB)
#define SM_STK    32768    // uint4[4096] 65536 (chunk stacks; stage-c out) | counting: encArr 16KB + sPart 4KB
#define SM_DENSE  98304    // uint4[4096] 65536 (stage-b out)              | scatter: rLoc f[4096]
#define SM_FSTART 163840   // int[4097] 16388
#define SM_FMEAN  180228   // float[4096] 16384
#define SM_CNTA   196612   // int[1024] 4096
#define SM_CNTB   200708   // int[32] 128
#define SM_RED    200836   // float[96] 384
#define SM_WHO    201220   // u32[2]
#define SM_NB     201228   // int
#define SMEM_BYTES 201248

__global__ __launch_bounds__(NTHREADS, 1)
void fusedKernel(const float* __restrict__ yhat,
                 const float* __restrict__ ytar,
                 float* __restrict__ out) {
    extern __shared__ char sm[];
    u64*   kArr   = (u64*)(sm + SM_KARR);
    float* fArr   = (float*)(sm + SM_KARR);     // counting overlay
    uint4* stk    = (uint4*)(sm + SM_STK);
    u32*   encArr = (u32*)(sm + SM_STK);        // counting overlay (16KB)
    u32*   sPart  = (u32*)(sm + SM_STK + 16384);// counting overlay (4KB)
    uint4* dense  = (uint4*)(sm + SM_DENSE);
    float* rLoc   = (float*)(sm + SM_DENSE);    // scatter overlay (after merge)
    int*   fStart = (int*)(sm + SM_FSTART);
    float* fMean  = (float*)(sm + SM_FMEAN);
    int*   cntA   = (int*)(sm + SM_CNTA);
    int*   cntB   = (int*)(sm + SM_CNTB);
    float* red    = (float*)(sm + SM_RED);
    u32*   shWho  = (u32*)(sm + SM_WHO);
    int*   nbPtr  = (int*)(sm + SM_NB);

    const int tid  = threadIdx.x;
    const int lane = tid & 31;
    const int wrp  = tid >> 5;
    const int row  = blockIdx.x >> 6;
    const int ctaSlot = blockIdx.x & (NCTA_ROW - 1);
    const float* src = row ? ytar : yhat;

    // ============ Phase 1: dual-pipe rank-by-counting (128 CTAs) ============
    {
        float4 v = ((const float4*)src)[tid];
        ((float4*)fArr)[tid] = v;
        uint4 ev;
        ev.x = encodeVal(v.x); ev.y = encodeVal(v.y);
        ev.z = encodeVal(v.z); ev.w = encodeVal(v.w);
        ((uint4*)encArr)[tid] = ev;
    }
    __syncthreads();

    {
        // lane = target, warp = value segment (256 values). First 128 values
        // compared as float (fma pipe), last 128 as encoded u32 (alu pipe).
        const int seg = wrp & 15;
        const int g   = wrp >> 4;
        const int ii  = ctaSlot * SLICE + g * 32 + lane;
        const float vi = fArr[ii];
        const u32   ei = encArr[ii];
        const float4* fq = (const float4*)(fArr + seg * 256);
        const uint4*  uq = (const uint4*)(encArr + seg * 256);
        float cf = 0.f;
        u32   ci = 0;
#pragma unroll 16
        for (int t = 0; t < 32; ++t) {
            float4 f = fq[t];           // values [seg*256, +128)
            uint4  u = uq[t + 32];      // values [seg*256+128, +128)
            cmpAccF(cf, f.x, vi); cmpAccU(ci, u.x, ei);
            cmpAccF(cf, f.y, vi); cmpAccU(ci, u.y, ei);
            cmpAccF(cf, f.z, vi); cmpAccU(ci, u.z, ei);
            cmpAccF(cf, f.w, vi); cmpAccU(ci, u.w, ei);
        }
        sPart[wrp * 32 + lane] = ci + (u32)cf;
    }
    __syncthreads();

    if (tid < SLICE) {
        int g = tid >> 5, ln = tid & 31;
        u32 pos = 0;
#pragma unroll
        for (int s = 0; s < 16; ++s)
            pos += sPart[(g * 16 + s) * 32 + ln];
        // pos = # strictly greater; ties get distinct slots via global ticket
        const int i = ctaSlot * SLICE + tid;
        const u32 en = encArr[i];
        u32 tick = atomicAdd(&g_tick[row][pos], 1u);
        g_keys[row][pos + tick] = ((u64)en << 32) | (u32)i;
    }

    // ============ gate 1: last CTA per row continues; rest exit ============
    __threadfence();
    __syncthreads();
    if (tid == 0) shWho[0] = atomicAdd(&g_cnt[row], 1);
    __syncthreads();
    if (shWho[0] != NCTA_ROW - 1) return;
    __threadfence();   // acquire other CTAs' g_keys writes

    // ============ Phase 2: PAV (1 CTA per row) ============
    {
        const u64* gk = g_keys[row];
#pragma unroll
        for (int m = 0; m < 4; m++) {
            int i = tid + m * NTHREADS;
            kArr[i] = gk[i];
        }
    }
    __syncthreads();

    // (a) per-thread chunk PAV, CHUNK=4, all-float state (exact: |sumW| < 2^24)
    {
        const int base = tid * CHUNK;
        float w  = (float)(N - base);            // w(i) = N - i, running
        float tS = decodeVal((u32)(kArr[base] >> 32));
        float tW = w, tC = 1.f;
        float tNum = tS - tW;
        int   tSt = base, sp = 0;
#pragma unroll
        for (int i2 = 1; i2 < CHUNK; ++i2) {
            int i = base + i2;
            w -= 1.f;
            float s = decodeVal((u32)(kArr[i] >> 32));
            float cS = s, cW = w, cC = 1.f, cNum = s - w;
            int   cSt = i;
            while (tNum * cC < cNum * tC) {      // pool
                cS += tS; cW += tW; cC += tC; cSt = tSt;
                cNum = cS - cW;
                if (sp == 0) { tC = 0.f; break; }
                sp--;
                uint4 a = stk[base + sp];
                tS = __uint_as_float(a.x); tW = __uint_as_float(a.y);
                tC = __uint_as_float(a.z); tSt = (int)a.w;
                tNum = tS - tW;
            }
            if (tC > 0.f) { stk[base + sp] = packAtom(tS, tW, tC, tSt); sp++; }
            tS = cS; tW = cW; tC = cC; tSt = cSt; tNum = cNum;
        }
        stk[base + sp] = packAtom(tS, tW, tC, tSt); sp++;
        cntA[tid] = sp;
    }
    __syncthreads();

    // (b) warp 0: lane k merges chunk lists [32k, 32k+32) -> dense[128k..]
    //     (c) lane 0 merges the 32 results -> stk[0..], nb atoms.
    if (wrp == 0) {
        cntB[lane] = mergeLists(stk, CHUNK, cntA, 32 * lane, 32, dense + 128 * lane);
        __syncwarp();
        if (lane == 0)
            *nbPtr = mergeLists(dense, 128, cntB, 0, 32, stk);
    }
    __syncthreads();

    const int nb = *nbPtr;
    for (int b = tid; b < nb; b += NTHREADS) {
        uint4 a = stk[b];
        fStart[b] = (int)a.w;
        fMean[b]  = (__uint_as_float(a.x) - __uint_as_float(a.y))
                    / __uint_as_float(a.z);
    }
    if (tid == 0) fStart[nb] = N;
    __syncthreads();

    // ---- scatter + own-row moments (rLoc overlays dense; merge done) ----
    float sR = 0.f, sR2 = 0.f;
#pragma unroll
    for (int m = 0; m < 4; m++) {
        int i = tid + m * NTHREADS;
        u64 kk = kArr[i];
        float s = decodeVal((u32)(kk >> 32));
        int  id = (int)(kk & 0xFFFFFFFFu);
        int lo = 0, hi = nb - 1;
        while (lo < hi) {
            int mid = (lo + hi + 1) >> 1;
            if (fStart[mid] <= i) lo = mid; else hi = mid - 1;
        }
        float r = s - fMean[lo] - 2048.5f;     // shift is Spearman-invariant
        g_rank[row][id] = r;
        rLoc[id] = r;
        sR  += r;
        sR2 += r * r;
    }

    // BCE split across the two PAV CTAs: row r handles [r*2048, r*2048+2048)
    float B = 0.f;
    {
        const int base = row * (N / 2);
        float2 x2 = ((const float2*)(yhat + base))[tid];
        float2 y2 = ((const float2*)(ytar + base))[tid];
        B += fmaxf(x2.x, 0.f) + log1pf(expf(-fabsf(x2.x))) - x2.x * y2.x;
        B += fmaxf(x2.y, 0.f) + log1pf(expf(-fabsf(x2.y))) - x2.y * y2.y;
    }
    blockReduce3(sR, sR2, B, red);
    if (tid == 0) {
        g_sum[row]   = sR;
        g_sumsq[row] = sR2;
        g_bce2[row]  = B;
    }

    // ============ gate 2: second of the two row CTAs finishes ============
    __threadfence();
    __syncthreads();
    if (tid == 0) shWho[1] = atomicAdd(&g_cnt2, 1);
    __syncthreads();
    if (shWho[1] != 1) return;
    __threadfence();   // acquire other row's ranks + partials

    {
        const float* other = g_rank[1 - row];
        float cr = 0.f;
#pragma unroll
        for (int m = 0; m < 4; m++) {
            int i = tid + m * NTHREADS;
            cr += other[i] * rLoc[i];
            g_tick[0][i] = 0;            // reset tickets for next replay
            g_tick[1][i] = 0;
        }
        cr = blockReduceSum(cr, red);
        if (tid == 0) {
            float invN = 1.0f / (float)N;
            float mp = g_sum[0] * invN, mt = g_sum[1] * invN;
            float varP = g_sumsq[0] - (float)N * mp * mp;
            float varT = g_sumsq[1] - (float)N * mt * mt;
            float cov  = cr - (float)N * mp * mt;
            float sp   = cov * rsqrtf(varP * varT);
            out[0] = (1.0f - sp) + (g_bce2[0] + g_bce2[1]) * invN;
            g_cnt[0] = 0; g_cnt[1] = 0; g_cnt2 = 0;   // reset for graph replay
        }
    }
}

extern "C" void kernel_launch(void* const* d_in, const int* in_sizes, int n_in,
                              void* d_out, int out_size) {
    const float* yhat = (const float*)d_in[0];
    const float* ytar = (const float*)d_in[1];
    float* out = (float*)d_out;
    cudaFuncSetAttribute(fusedKernel,
                         cudaFuncAttributeMaxDynamicSharedMemorySize, SMEM_BYTES);
    fusedKernel<<<2 * NCTA_ROW, NTHREADS, SMEM_BYTES>>>(yhat, ytar, out);
}

// round 15
// speedup vs baseline: 1.2503x; 1.2503x over previous
#include <cuda_runtime.h>
#include <math.h>

#define N 4096
#define NTHREADS 1024
#define NCTA_ROW 64
#define SLICE 64
#define NCHUNK 256
#define CHUNK 16

typedef unsigned long long u64;
typedef unsigned int u32;

__device__ u64   g_keys[2][N];
__device__ float g_rank[2][N];
__device__ float g_sum[2], g_sumsq[2], g_bce2[2];
__device__ u32   g_tick[2][N];     // tie tickets (reset by PAV CTAs each launch)
__device__ u32   g_cnt[2];
__device__ u32   g_cnt2;

// ---- float -> order-preserving uint (ascending), exact inverse ----
__device__ __forceinline__ u32 encodeVal(float v) {
    u32 b = __float_as_uint(v);
    return (b & 0x80000000u) ? ~b : (b | 0x80000000u);
}
__device__ __forceinline__ float decodeVal(u32 e) {
    return (e & 0x80000000u) ? __uint_as_float(e ^ 0x80000000u)
                             : __uint_as_float(~e);
}

// predicated accumulate, guaranteed 2-instr forms on separate pipes
__device__ __forceinline__ void cmpAccF(float& cf, float a, float vi) {
    asm("{.reg .pred p; setp.gt.f32 p, %1, %2;\n\t"
        "@p add.f32 %0, %0, 0f3F800000;}\n"
        : "+f"(cf) : "f"(a), "f"(vi));
}
__device__ __forceinline__ void cmpAccU(u32& c, u32 a, u32 ei) {
    asm("{.reg .pred p; setp.gt.u32 p, %1, %2;\n\t"
        "@p add.u32 %0, %0, 1;}\n"
        : "+r"(c) : "r"(a), "r"(ei));
}

__device__ __forceinline__ uint4 packAtom(float S, float W, float C, int st) {
    uint4 a;
    a.x = __float_as_uint(S); a.y = __float_as_uint(W);
    a.z = __float_as_uint(C); a.w = (u32)st;
    return a;
}

// Serially merge nLists PAV block-lists (atoms in stream order) onto D.
// Identical pooling arithmetic to the serial PAV stream -> identical result.
__device__ __forceinline__ int mergeLists(const uint4* srcBase, int stride,
                                          const int* cnts, int first, int nLists,
                                          uint4* D) {
    float tS = 0.f, tW = 0.f, tC = 0.f, tNum = 0.f;
    int   tSt = 0, sp = 0;
    bool init = false;
    for (int L = 0; L < nLists; L++) {
        const uint4* src = srcBase + (first + L) * stride;
        int c = cnts[first + L];
        for (int r = 0; r < c; r++) {
            uint4 b = src[r];
            float cS = __uint_as_float(b.x), cW = __uint_as_float(b.y);
            float cC = __uint_as_float(b.z);
            int   cSt = (int)b.w;
            float cNum = cS - cW;
            if (!init) { tS = cS; tW = cW; tC = cC; tSt = cSt; tNum = cNum; init = true; continue; }
            while (tNum * cC < cNum * tC) {      // pool
                cS += tS; cW += tW; cC += tC; cSt = tSt;
                cNum = cS - cW;
                if (sp == 0) { tC = 0.f; break; }
                sp--;
                uint4 p = D[sp];
                tS = __uint_as_float(p.x); tW = __uint_as_float(p.y);
                tC = __uint_as_float(p.z); tSt = (int)p.w;
                tNum = tS - tW;
            }
            if (tC > 0.f) D[sp++] = packAtom(tS, tW, tC, tSt);
            tS = cS; tW = cW; tC = cC; tSt = cSt; tNum = cNum;
        }
    }
    D[sp++] = packAtom(tS, tW, tC, tSt);
    return sp;
}

__device__ __forceinline__ float blockReduceSum(float v, float* scratch) {
#pragma unroll
    for (int o = 16; o; o >>= 1) v += __shfl_down_sync(0xffffffffu, v, o);
    int w = threadIdx.x >> 5, l = threadIdx.x & 31;
    __syncthreads();
    if (l == 0) scratch[w] = v;
    __syncthreads();
    if (w == 0) {
        float t = scratch[l];   // exactly 32 warps
#pragma unroll
        for (int o = 16; o; o >>= 1) t += __shfl_down_sync(0xffffffffu, t, o);
        if (l == 0) scratch[0] = t;
    }
    __syncthreads();
    return scratch[0];
}

// fused 3-way block reduction: one scratch round instead of three
__device__ __forceinline__ void blockReduce3(float& a, float& b, float& c,
                                             float* scratch) {
#pragma unroll
    for (int o = 16; o; o >>= 1) {
        a += __shfl_down_sync(0xffffffffu, a, o);
        b += __shfl_down_sync(0xffffffffu, b, o);
        c += __shfl_down_sync(0xffffffffu, c, o);
    }
    int w = threadIdx.x >> 5, l = threadIdx.x & 31;
    __syncthreads();
    if (l == 0) { scratch[w] = a; scratch[32 + w] = b; scratch[64 + w] = c; }
    __syncthreads();
    if (w == 0) {
        float ta = scratch[l], tb = scratch[32 + l], tc = scratch[64 + l];
#pragma unroll
        for (int o = 16; o; o >>= 1) {
            ta += __shfl_down_sync(0xffffffffu, ta, o);
            tb += __shfl_down_sync(0xffffffffu, tb, o);
            tc += __shfl_down_sync(0xffffffffu, tc, o);
        }
        if (l == 0) { scratch[0] = ta; scratch[32] = tb; scratch[64] = tc; }
    }
    __syncthreads();
    a = scratch[0]; b = scratch[32]; c = scratch[64];
}

// ---- SMEM byte offsets (R13 layout) ----
#define SM_KARR   0        // u64[4096] 32768   | counting: fArr f32[4096] (16KB)
#define SM_STK    32768    // uint4[4096] 65536 | counting: encArr 16KB + sPart 4KB
#define SM_DENSE  98304    // uint4[4096] 65536 | scatter: rLoc f[4096]
#define SM_FSTART 163840   // int[4097] 16388
#define SM_FMEAN  180228   // float[4096] 16384
#define SM_CNTA   196612   // int[256] 1024
#define SM_CNTB   197636   // int[256] 1024
#define SM_RED    198660   // float[96] 384
#define SM_WHO    199044   // u32[2]
#define SM_NB     199052   // int
#define SMEM_BYTES 199072

__global__ __launch_bounds__(NTHREADS, 1)
void fusedKernel(const float* __restrict__ yhat,
                 const float* __restrict__ ytar,
                 float* __restrict__ out) {
    extern __shared__ char sm[];
    u64*   kArr   = (u64*)(sm + SM_KARR);
    float* fArr   = (float*)(sm + SM_KARR);     // counting overlay
    uint4* stk    = (uint4*)(sm + SM_STK);
    u32*   encArr = (u32*)(sm + SM_STK);        // counting overlay (16KB)
    u32*   sPart  = (u32*)(sm + SM_STK + 16384);// counting overlay (4KB)
    uint4* dense  = (uint4*)(sm + SM_DENSE);
    float* rLoc   = (float*)(sm + SM_DENSE);    // scatter overlay (after merge)
    int*   fStart = (int*)(sm + SM_FSTART);
    float* fMean  = (float*)(sm + SM_FMEAN);
    int*   cntA   = (int*)(sm + SM_CNTA);
    int*   cntB   = (int*)(sm + SM_CNTB);
    float* red    = (float*)(sm + SM_RED);
    u32*   shWho  = (u32*)(sm + SM_WHO);
    int*   nbPtr  = (int*)(sm + SM_NB);

    const int tid  = threadIdx.x;
    const int lane = tid & 31;
    const int wrp  = tid >> 5;
    const int row  = blockIdx.x >> 6;
    const int ctaSlot = blockIdx.x & (NCTA_ROW - 1);
    const float* src = row ? ytar : yhat;

    // ============ Phase 1: dual-pipe rank-by-counting (128 CTAs) ============
    {
        float4 v = ((const float4*)src)[tid];
        ((float4*)fArr)[tid] = v;
        uint4 ev;
        ev.x = encodeVal(v.x); ev.y = encodeVal(v.y);
        ev.z = encodeVal(v.z); ev.w = encodeVal(v.w);
        ((uint4*)encArr)[tid] = ev;
    }
    __syncthreads();

    {
        // lane = target, warp = value segment (256 values). First 128 values
        // compared as float (fma pipe), last 128 as encoded u32 (alu pipe).
        const int seg = wrp & 15;
        const int g   = wrp >> 4;
        const int ii  = ctaSlot * SLICE + g * 32 + lane;
        const float vi = fArr[ii];
        const u32   ei = encArr[ii];
        const float4* fq = (const float4*)(fArr + seg * 256);
        const uint4*  uq = (const uint4*)(encArr + seg * 256);
        float cf = 0.f;
        u32   ci = 0;
#pragma unroll 16
        for (int t = 0; t < 32; ++t) {
            float4 f = fq[t];           // values [seg*256, +128)
            uint4  u = uq[t + 32];      // values [seg*256+128, +128)
            cmpAccF(cf, f.x, vi); cmpAccU(ci, u.x, ei);
            cmpAccF(cf, f.y, vi); cmpAccU(ci, u.y, ei);
            cmpAccF(cf, f.z, vi); cmpAccU(ci, u.z, ei);
            cmpAccF(cf, f.w, vi); cmpAccU(ci, u.w, ei);
        }
        sPart[wrp * 32 + lane] = ci + (u32)cf;
    }
    __syncthreads();

    if (tid < SLICE) {
        int g = tid >> 5, ln = tid & 31;
        u32 pos = 0;
#pragma unroll
        for (int s = 0; s < 16; ++s)
            pos += sPart[(g * 16 + s) * 32 + ln];
        // pos = # strictly greater; ties get distinct slots via global ticket
        const int i = ctaSlot * SLICE + tid;
        const u32 en = encArr[i];
        u32 tick = atomicAdd(&g_tick[row][pos], 1u);
        g_keys[row][pos + tick] = ((u64)en << 32) | (u32)i;
    }

    // ============ gate 1: last CTA per row continues; rest exit ============
    __threadfence();
    __syncthreads();
    if (tid == 0) shWho[0] = atomicAdd(&g_cnt[row], 1);
    __syncthreads();
    if (shWho[0] != NCTA_ROW - 1) return;
    __threadfence();   // acquire other CTAs' g_keys writes

    // ============ Phase 2: PAV (1 CTA per row) ============
    {
        const u64* gk = g_keys[row];
#pragma unroll
        for (int m = 0; m < 4; m++) {
            int i = tid + m * NTHREADS;
            kArr[i] = gk[i];
            g_tick[row][i] = 0;          // reset own row's tickets (counting done)
        }
    }
    __syncthreads();

    // per-chunk PAV, CHUNK=16, all-float block state (exact: |sumW| < 2^24)
    if (tid < NCHUNK) {
        const int base = tid * CHUNK;
        float w  = (float)(N - base);            // w(i) = N - i, running
        float tS = decodeVal((u32)(kArr[base] >> 32));
        float tW = w, tC = 1.f;
        float tNum = tS - tW;
        int   tSt = base, sp = 0;
        for (int i = base + 1; i < base + CHUNK; ++i) {
            w -= 1.f;
            float s = decodeVal((u32)(kArr[i] >> 32));
            float cS = s, cW = w, cC = 1.f, cNum = s - w;
            int   cSt = i;
            while (tNum * cC < cNum * tC) {      // pool
                cS += tS; cW += tW; cC += tC; cSt = tSt;
                cNum = cS - cW;
                if (sp == 0) { tC = 0.f; break; }
                sp--;
                uint4 a = stk[base + sp];
                tS = __uint_as_float(a.x); tW = __uint_as_float(a.y);
                tC = __uint_as_float(a.z); tSt = (int)a.w;
                tNum = tS - tW;
            }
            if (tC > 0.f) { stk[base + sp] = packAtom(tS, tW, tC, tSt); sp++; }
            tS = cS; tW = cW; tC = cC; tSt = cSt; tNum = cNum;
        }
        stk[base + sp] = packAtom(tS, tW, tC, tSt); sp++;
        cntA[tid] = sp;
    }
    __syncthreads();

    // ---- 4-way tree merge: 4 levels, per-THREAD independent merges ----
    // 256 -> 64 -> 16 -> 4 -> 1; each thread streams <=4 short lists.
    if (tid < 64)
        cntB[tid] = mergeLists(stk, CHUNK, cntA, 4 * tid, 4, dense + tid * 64);
    __syncthreads();
    if (tid < 16)
        cntA[tid] = mergeLists(dense, 64, cntB, 4 * tid, 4, stk + tid * 256);
    __syncthreads();
    if (tid < 4)
        cntB[tid] = mergeLists(stk, 256, cntA, 4 * tid, 4, dense + tid * 1024);
    __syncthreads();
    if (tid == 0)
        *nbPtr = mergeLists(dense, 1024, cntB, 0, 4, stk);
    __syncthreads();

    const int nb = *nbPtr;
    for (int b = tid; b < nb; b += NTHREADS) {
        uint4 a = stk[b];
        fStart[b] = (int)a.w;
        fMean[b]  = (__uint_as_float(a.x) - __uint_as_float(a.y))
                    / __uint_as_float(a.z);
    }
    if (tid == 0) fStart[nb] = N;
    __syncthreads();

    // ---- scatter + own-row moments (rLoc overlays dense; merge done) ----
    float sR = 0.f, sR2 = 0.f;
#pragma unroll
    for (int m = 0; m < 4; m++) {
        int i = tid + m * NTHREADS;
        u64 kk = kArr[i];
        float s = decodeVal((u32)(kk >> 32));
        int  id = (int)(kk & 0xFFFFFFFFu);
        int lo = 0, hi = nb - 1;
        while (lo < hi) {
            int mid = (lo + hi + 1) >> 1;
            if (fStart[mid] <= i) lo = mid; else hi = mid - 1;
        }
        float r = s - fMean[lo] - 2048.5f;     // shift is Spearman-invariant
        g_rank[row][id] = r;
        rLoc[id] = r;
        sR  += r;
        sR2 += r * r;
    }

    // BCE split across the two PAV CTAs: row r handles [r*2048, +2048)
    float B = 0.f;
    {
        const int base = row * (N / 2);
        float2 x2 = ((const float2*)(yhat + base))[tid];
        float2 y2 = ((const float2*)(ytar + base))[tid];
        B += fmaxf(x2.x, 0.f) + log1pf(expf(-fabsf(x2.x))) - x2.x * y2.x;
        B += fmaxf(x2.y, 0.f) + log1pf(expf(-fabsf(x2.y))) - x2.y * y2.y;
    }
    blockReduce3(sR, sR2, B, red);
    if (tid == 0) {
        g_sum[row]   = sR;
        g_sumsq[row] = sR2;
        g_bce2[row]  = B;
    }

    // ============ gate 2: second of the two row CTAs finishes ============
    __threadfence();
    __syncthreads();
    if (tid == 0) shWho[1] = atomicAdd(&g_cnt2, 1);
    __syncthreads();
    if (shWho[1] != 1) return;
    __threadfence();   // acquire other row's ranks + partials

    {
        const float* other = g_rank[1 - row];
        float cr = 0.f;
#pragma unroll
        for (int m = 0; m < 4; m++) {
            int i = tid + m * NTHREADS;
            cr += other[i] * rLoc[i];
        }
        cr = blockReduceSum(cr, red);
        if (tid == 0) {
            float invN = 1.0f / (float)N;
            float mp = g_sum[0] * invN, mt = g_sum[1] * invN;
            float varP = g_sumsq[0] - (float)N * mp * mp;
            float varT = g_sumsq[1] - (float)N * mt * mt;
            float cov  = cr - (float)N * mp * mt;
            float sp   = cov * rsqrtf(varP * varT);
            out[0] = (1.0f - sp) + (g_bce2[0] + g_bce2[1]) * invN;
            g_cnt[0] = 0; g_cnt[1] = 0; g_cnt2 = 0;   // reset for graph replay
        }
    }
}

extern "C" void kernel_launch(void* const* d_in, const int* in_sizes, int n_in,
                              void* d_out, int out_size) {
    const float* yhat = (const float*)d_in[0];
    const float* ytar = (const float*)d_in[1];
    float* out = (float*)d_out;
    cudaFuncSetAttribute(fusedKernel,
                         cudaFuncAttributeMaxDynamicSharedMemorySize, SMEM_BYTES);
    fusedKernel<<<2 * NCTA_ROW, NTHREADS, SMEM_BYTES>>>(yhat, ytar, out);
}

// round 16
// speedup vs baseline: 1.8358x; 1.4684x over previous
#include <cuda_runtime.h>
#include <math.h>

#define N 4096
#define NTHREADS 1024
#define NCTA_ROW 64
#define SLICE 64
#define NCHUNK 256
#define CHUNK 16

typedef unsigned long long u64;
typedef unsigned int u32;

__device__ u64   g_keys[2][N];
__device__ float g_rank[2][N];
__device__ float g_sum[2], g_sumsq[2], g_bce2[2];
__device__ u32   g_tick[2][N];     // tie tickets (reset by PAV CTAs each launch)
__device__ u32   g_cnt[2];
__device__ u32   g_cnt2;

// ---- float -> order-preserving uint (ascending), exact inverse ----
__device__ __forceinline__ u32 encodeVal(float v) {
    u32 b = __float_as_uint(v);
    return (b & 0x80000000u) ? ~b : (b | 0x80000000u);
}
__device__ __forceinline__ float decodeVal(u32 e) {
    return (e & 0x80000000u) ? __uint_as_float(e ^ 0x80000000u)
                             : __uint_as_float(~e);
}

// predicated accumulate, guaranteed 2-instr forms on separate pipes
__device__ __forceinline__ void cmpAccF(float& cf, float a, float vi) {
    asm("{.reg .pred p; setp.gt.f32 p, %1, %2;\n\t"
        "@p add.f32 %0, %0, 0f3F800000;}\n"
        : "+f"(cf) : "f"(a), "f"(vi));
}
__device__ __forceinline__ void cmpAccU(u32& c, u32 a, u32 ei) {
    asm("{.reg .pred p; setp.gt.u32 p, %1, %2;\n\t"
        "@p add.u32 %0, %0, 1;}\n"
        : "+r"(c) : "r"(a), "r"(ei));
}

__device__ __forceinline__ uint4 packAtom(float S, float W, float C, int st) {
    uint4 a;
    a.x = __float_as_uint(S); a.y = __float_as_uint(W);
    a.z = __float_as_uint(C); a.w = (u32)st;
    return a;
}

__device__ __forceinline__ float blockReduceSum(float v, float* scratch) {
#pragma unroll
    for (int o = 16; o; o >>= 1) v += __shfl_down_sync(0xffffffffu, v, o);
    int w = threadIdx.x >> 5, l = threadIdx.x & 31;
    __syncthreads();
    if (l == 0) scratch[w] = v;
    __syncthreads();
    if (w == 0) {
        float t = scratch[l];   // exactly 32 warps
#pragma unroll
        for (int o = 16; o; o >>= 1) t += __shfl_down_sync(0xffffffffu, t, o);
        if (l == 0) scratch[0] = t;
    }
    __syncthreads();
    return scratch[0];
}

// fused 3-way block reduction: one scratch round instead of three
__device__ __forceinline__ void blockReduce3(float& a, float& b, float& c,
                                             float* scratch) {
#pragma unroll
    for (int o = 16; o; o >>= 1) {
        a += __shfl_down_sync(0xffffffffu, a, o);
        b += __shfl_down_sync(0xffffffffu, b, o);
        c += __shfl_down_sync(0xffffffffu, c, o);
    }
    int w = threadIdx.x >> 5, l = threadIdx.x & 31;
    __syncthreads();
    if (l == 0) { scratch[w] = a; scratch[32 + w] = b; scratch[64 + w] = c; }
    __syncthreads();
    if (w == 0) {
        float ta = scratch[l], tb = scratch[32 + l], tc = scratch[64 + l];
#pragma unroll
        for (int o = 16; o; o >>= 1) {
            ta += __shfl_down_sync(0xffffffffu, ta, o);
            tb += __shfl_down_sync(0xffffffffu, tb, o);
            tc += __shfl_down_sync(0xffffffffu, tc, o);
        }
        if (l == 0) { scratch[0] = ta; scratch[32] = tb; scratch[64] = tc; }
    }
    __syncthreads();
    a = scratch[0]; b = scratch[32]; c = scratch[64];
}

// ---- SMEM byte offsets (R13 layout) ----
#define SM_KARR   0        // u64[4096] 32768   | counting: fArr f32[4096] (16KB)
#define SM_STK    32768    // uint4[4096] 65536 | counting: encArr 16KB + sPart 4KB
#define SM_DENSE  98304    // uint4[4096] 65536 | scatter: rLoc f[4096]
#define SM_FSTART 163840   // int[4097] 16388
#define SM_FMEAN  180228   // float[4096] 16384
#define SM_CNTA   196612   // int[256] 1024
#define SM_CNTB   197636   // int[256] 1024
#define SM_RED    198660   // float[96] 384
#define SM_WHO    199044   // u32[2]
#define SM_NB     199052   // int
#define SMEM_BYTES 199072

__global__ __launch_bounds__(NTHREADS, 1)
void fusedKernel(const float* __restrict__ yhat,
                 const float* __restrict__ ytar,
                 float* __restrict__ out) {
    extern __shared__ char sm[];
    u64*   kArr   = (u64*)(sm + SM_KARR);
    float* fArr   = (float*)(sm + SM_KARR);     // counting overlay
    uint4* stk    = (uint4*)(sm + SM_STK);
    u32*   encArr = (u32*)(sm + SM_STK);        // counting overlay (16KB)
    u32*   sPart  = (u32*)(sm + SM_STK + 16384);// counting overlay (4KB)
    uint4* dense  = (uint4*)(sm + SM_DENSE);
    float* rLoc   = (float*)(sm + SM_DENSE);    // scatter overlay (after merge)
    int*   fStart = (int*)(sm + SM_FSTART);
    float* fMean  = (float*)(sm + SM_FMEAN);
    int*   cntA   = (int*)(sm + SM_CNTA);
    int*   cntB   = (int*)(sm + SM_CNTB);
    float* red    = (float*)(sm + SM_RED);
    u32*   shWho  = (u32*)(sm + SM_WHO);
    int*   nbPtr  = (int*)(sm + SM_NB);

    const int tid  = threadIdx.x;
    const int lane = tid & 31;
    const int wrp  = tid >> 5;
    const int row  = blockIdx.x >> 6;
    const int ctaSlot = blockIdx.x & (NCTA_ROW - 1);
    const float* src = row ? ytar : yhat;

    // ============ Phase 1: dual-pipe rank-by-counting (128 CTAs) ============
    {
        float4 v = ((const float4*)src)[tid];
        ((float4*)fArr)[tid] = v;
        uint4 ev;
        ev.x = encodeVal(v.x); ev.y = encodeVal(v.y);
        ev.z = encodeVal(v.z); ev.w = encodeVal(v.w);
        ((uint4*)encArr)[tid] = ev;
    }
    __syncthreads();

    {
        // lane = target, warp = value segment (256 values). First 128 values
        // compared as float (fma pipe), last 128 as encoded u32 (alu pipe).
        const int seg = wrp & 15;
        const int g   = wrp >> 4;
        const int ii  = ctaSlot * SLICE + g * 32 + lane;
        const float vi = fArr[ii];
        const u32   ei = encArr[ii];
        const float4* fq = (const float4*)(fArr + seg * 256);
        const uint4*  uq = (const uint4*)(encArr + seg * 256);
        float cf = 0.f;
        u32   ci = 0;
#pragma unroll 16
        for (int t = 0; t < 32; ++t) {
            float4 f = fq[t];           // values [seg*256, +128)
            uint4  u = uq[t + 32];      // values [seg*256+128, +128)
            cmpAccF(cf, f.x, vi); cmpAccU(ci, u.x, ei);
            cmpAccF(cf, f.y, vi); cmpAccU(ci, u.y, ei);
            cmpAccF(cf, f.z, vi); cmpAccU(ci, u.z, ei);
            cmpAccF(cf, f.w, vi); cmpAccU(ci, u.w, ei);
        }
        sPart[wrp * 32 + lane] = ci + (u32)cf;
    }
    __syncthreads();

    if (tid < SLICE) {
        int g = tid >> 5, ln = tid & 31;
        u32 pos = 0;
#pragma unroll
        for (int s = 0; s < 16; ++s)
            pos += sPart[(g * 16 + s) * 32 + ln];
        // pos = # strictly greater; ties get distinct slots via global ticket
        const int i = ctaSlot * SLICE + tid;
        const u32 en = encArr[i];
        u32 tick = atomicAdd(&g_tick[row][pos], 1u);
        g_keys[row][pos + tick] = ((u64)en << 32) | (u32)i;
    }

    // ============ gate 1: last CTA per row continues; rest exit ============
    __threadfence();
    __syncthreads();
    if (tid == 0) shWho[0] = atomicAdd(&g_cnt[row], 1);
    __syncthreads();
    if (shWho[0] != NCTA_ROW - 1) return;
    __threadfence();   // acquire other CTAs' g_keys writes

    // ============ Phase 2: PAV (1 CTA per row) ============
    {
        const u64* gk = g_keys[row];
#pragma unroll
        for (int m = 0; m < 4; m++) {
            int i = tid + m * NTHREADS;
            kArr[i] = gk[i];
            g_tick[row][i] = 0;          // reset own row's tickets (counting done)
        }
    }
    __syncthreads();

    // per-chunk PAV, CHUNK=16, all-float block state (exact: |sumW| < 2^24)
    if (tid < NCHUNK) {
        const int base = tid * CHUNK;
        float w  = (float)(N - base);            // w(i) = N - i, running
        float tS = decodeVal((u32)(kArr[base] >> 32));
        float tW = w, tC = 1.f;
        float tNum = tS - tW;
        int   tSt = base, sp = 0;
        for (int i = base + 1; i < base + CHUNK; ++i) {
            w -= 1.f;
            float s = decodeVal((u32)(kArr[i] >> 32));
            float cS = s, cW = w, cC = 1.f, cNum = s - w;
            int   cSt = i;
            while (tNum * cC < cNum * tC) {      // pool
                cS += tS; cW += tW; cC += tC; cSt = tSt;
                cNum = cS - cW;
                if (sp == 0) { tC = 0.f; break; }
                sp--;
                uint4 a = stk[base + sp];
                tS = __uint_as_float(a.x); tW = __uint_as_float(a.y);
                tC = __uint_as_float(a.z); tSt = (int)a.w;
                tNum = tS - tW;
            }
            if (tC > 0.f) { stk[base + sp] = packAtom(tS, tW, tC, tSt); sp++; }
            tS = cS; tW = cW; tC = cC; tSt = cSt; tNum = cNum;
        }
        stk[base + sp] = packAtom(tS, tW, tC, tSt); sp++;
        cntA[tid] = sp;
    }

    // ---- tree merge: 8 levels of parallel PAIRWISE merges (proven R13) ----
    // Left list's means strictly decrease -> replaying left never pools; only
    // the right list streams through pooling. Identical result to serial PAV.
    uint4* finBuf;
    {
        uint4* srcB = stk;   uint4* dstB = dense;
        int*   sCnt = cntA;  int*   dCnt = cntB;
        int NL = NCHUNK, S = CHUNK;
        while (NL > 1) {
            __syncthreads();
            if (tid < (NL >> 1)) {
                const uint4* L = srcB + (2 * tid) * S;
                const uint4* R = srcB + (2 * tid + 1) * S;
                uint4* D = dstB + tid * (2 * S);
                int la = sCnt[2 * tid], lb = sCnt[2 * tid + 1];
                // copy left list except its last block (held in registers)
                for (int j = 0; j < la - 1; j++) D[j] = L[j];
                uint4 a = L[la - 1];
                float tS = __uint_as_float(a.x), tW = __uint_as_float(a.y);
                float tC = __uint_as_float(a.z);
                int   tSt = (int)a.w;
                float tNum = tS - tW;
                int sp = la - 1;
                for (int r = 0; r < lb; r++) {
                    uint4 b = R[r];
                    float cS = __uint_as_float(b.x), cW = __uint_as_float(b.y);
                    float cC = __uint_as_float(b.z);
                    int   cSt = (int)b.w;
                    float cNum = cS - cW;
                    while (tNum * cC < cNum * tC) {
                        cS += tS; cW += tW; cC += tC; cSt = tSt;
                        cNum = cS - cW;
                        if (sp == 0) { tC = 0.f; break; }
                        sp--;
                        uint4 p = D[sp];
                        tS = __uint_as_float(p.x); tW = __uint_as_float(p.y);
                        tC = __uint_as_float(p.z); tSt = (int)p.w;
                        tNum = tS - tW;
                    }
                    if (tC > 0.f) { D[sp++] = packAtom(tS, tW, tC, tSt); }
                    tS = cS; tW = cW; tC = cC; tSt = cSt; tNum = cNum;
                }
                D[sp++] = packAtom(tS, tW, tC, tSt);
                dCnt[tid] = sp;
            }
            uint4* tb = srcB; srcB = dstB; dstB = tb;
            int*   tc = sCnt; sCnt = dCnt; dCnt = tc;
            NL >>= 1; S <<= 1;
        }
        __syncthreads();
        finBuf = srcB;                       // 8 levels -> back in stk
        if (tid == 0) *nbPtr = sCnt[0];
    }
    __syncthreads();

    const int nb = *nbPtr;
    for (int b = tid; b < nb; b += NTHREADS) {
        uint4 a = finBuf[b];
        fStart[b] = (int)a.w;
        fMean[b]  = (__uint_as_float(a.x) - __uint_as_float(a.y))
                    / __uint_as_float(a.z);
    }
    if (tid == 0) fStart[nb] = N;
    __syncthreads();

    // ---- scatter + own-row moments (rLoc overlays dense; merge done) ----
    float sR = 0.f, sR2 = 0.f;
#pragma unroll
    for (int m = 0; m < 4; m++) {
        int i = tid + m * NTHREADS;
        u64 kk = kArr[i];
        float s = decodeVal((u32)(kk >> 32));
        int  id = (int)(kk & 0xFFFFFFFFu);
        int lo = 0, hi = nb - 1;
        while (lo < hi) {
            int mid = (lo + hi + 1) >> 1;
            if (fStart[mid] <= i) lo = mid; else hi = mid - 1;
        }
        float r = s - fMean[lo] - 2048.5f;     // shift is Spearman-invariant
        g_rank[row][id] = r;
        rLoc[id] = r;
        sR  += r;
        sR2 += r * r;
    }

    // BCE split across the two PAV CTAs: row r handles [r*2048, +2048)
    float B = 0.f;
    {
        const int base = row * (N / 2);
        float2 x2 = ((const float2*)(yhat + base))[tid];
        float2 y2 = ((const float2*)(ytar + base))[tid];
        B += fmaxf(x2.x, 0.f) + log1pf(expf(-fabsf(x2.x))) - x2.x * y2.x;
        B += fmaxf(x2.y, 0.f) + log1pf(expf(-fabsf(x2.y))) - x2.y * y2.y;
    }
    blockReduce3(sR, sR2, B, red);
    if (tid == 0) {
        g_sum[row]   = sR;
        g_sumsq[row] = sR2;
        g_bce2[row]  = B;
    }

    // ============ gate 2: second of the two row CTAs finishes ============
    __threadfence();
    __syncthreads();
    if (tid == 0) shWho[1] = atomicAdd(&g_cnt2, 1);
    __syncthreads();
    if (shWho[1] != 1) return;
    __threadfence();   // acquire other row's ranks + partials

    {
        const float* other = g_rank[1 - row];
        float cr = 0.f;
#pragma unroll
        for (int m = 0; m < 4; m++) {
            int i = tid + m * NTHREADS;
            cr += other[i] * rLoc[i];
        }
        cr = blockReduceSum(cr, red);
        if (tid == 0) {
            float invN = 1.0f / (float)N;
            float mp = g_sum[0] * invN, mt = g_sum[1] * invN;
            float varP = g_sumsq[0] - (float)N * mp * mp;
            float varT = g_sumsq[1] - (float)N * mt * mt;
            float cov  = cr - (float)N * mp * mt;
            float sp   = cov * rsqrtf(varP * varT);
            out[0] = (1.0f - sp) + (g_bce2[0] + g_bce2[1]) * invN;
            g_cnt[0] = 0; g_cnt[1] = 0; g_cnt2 = 0;   // reset for graph replay
        }
    }
}

extern "C" void kernel_launch(void* const* d_in, const int* in_sizes, int n_in,
                              void* d_out, int out_size) {
    const float* yhat = (const float*)d_in[0];
    const float* ytar = (const float*)d_in[1];
    float* out = (float*)d_out;
    cudaFuncSetAttribute(fusedKernel,
                         cudaFuncAttributeMaxDynamicSharedMemorySize, SMEM_BYTES);
    fusedKernel<<<2 * NCTA_ROW, NTHREADS, SMEM_BYTES>>>(yhat, ytar, out);
}

// round 17
// speedup vs baseline: 1.8582x; 1.0122x over previous
#include <cuda_runtime.h>
#include <math.h>

#define N 4096
#define NTHREADS 1024
#define NCTA_ROW 64
#define SLICE 64
#define NCHUNK 512
#define CHUNK 8

typedef unsigned long long u64;
typedef unsigned int u32;

__device__ u64   g_keys[2][N];
__device__ float g_rank[2][N];
__device__ float g_sum[2], g_sumsq[2];
__device__ float g_part[2 * NCTA_ROW];   // per-CTA BCE partials
__device__ u32   g_tick[2][N];           // tie tickets (reset by PAV CTAs)
__device__ u32   g_cnt[2];
__device__ u32   g_cnt2;

// ---- float -> order-preserving uint (ascending), exact inverse ----
__device__ __forceinline__ u32 encodeVal(float v) {
    u32 b = __float_as_uint(v);
    return (b & 0x80000000u) ? ~b : (b | 0x80000000u);
}
__device__ __forceinline__ float decodeVal(u32 e) {
    return (e & 0x80000000u) ? __uint_as_float(e ^ 0x80000000u)
                             : __uint_as_float(~e);
}

// predicated accumulate, guaranteed 2-instr forms on separate pipes
__device__ __forceinline__ void cmpAccF(float& cf, float a, float vi) {
    asm("{.reg .pred p; setp.gt.f32 p, %1, %2;\n\t"
        "@p add.f32 %0, %0, 0f3F800000;}\n"
        : "+f"(cf) : "f"(a), "f"(vi));
}
__device__ __forceinline__ void cmpAccU(u32& c, u32 a, u32 ei) {
    asm("{.reg .pred p; setp.gt.u32 p, %1, %2;\n\t"
        "@p add.u32 %0, %0, 1;}\n"
        : "+r"(c) : "r"(a), "r"(ei));
}

__device__ __forceinline__ uint4 packAtom(float S, float W, float C, int st) {
    uint4 a;
    a.x = __float_as_uint(S); a.y = __float_as_uint(W);
    a.z = __float_as_uint(C); a.w = (u32)st;
    return a;
}

// Serially merge nLists PAV block-lists (atoms in stream order) onto D.
// Identical pooling arithmetic to the serial PAV stream -> identical result.
// Used ONLY single-threaded (no lane divergence).
__device__ __forceinline__ int mergeLists(const uint4* srcBase, int stride,
                                          const int* cnts, int first, int nLists,
                                          uint4* D) {
    float tS = 0.f, tW = 0.f, tC = 0.f, tNum = 0.f;
    int   tSt = 0, sp = 0;
    bool init = false;
    for (int L = 0; L < nLists; L++) {
        const uint4* src = srcBase + (first + L) * stride;
        int c = cnts[first + L];
        for (int r = 0; r < c; r++) {
            uint4 b = src[r];
            float cS = __uint_as_float(b.x), cW = __uint_as_float(b.y);
            float cC = __uint_as_float(b.z);
            int   cSt = (int)b.w;
            float cNum = cS - cW;
            if (!init) { tS = cS; tW = cW; tC = cC; tSt = cSt; tNum = cNum; init = true; continue; }
            while (tNum * cC < cNum * tC) {      // pool
                cS += tS; cW += tW; cC += tC; cSt = tSt;
                cNum = cS - cW;
                if (sp == 0) { tC = 0.f; break; }
                sp--;
                uint4 p = D[sp];
                tS = __uint_as_float(p.x); tW = __uint_as_float(p.y);
                tC = __uint_as_float(p.z); tSt = (int)p.w;
                tNum = tS - tW;
            }
            if (tC > 0.f) D[sp++] = packAtom(tS, tW, tC, tSt);
            tS = cS; tW = cW; tC = cC; tSt = cSt; tNum = cNum;
        }
    }
    D[sp++] = packAtom(tS, tW, tC, tSt);
    return sp;
}

__device__ __forceinline__ float blockReduceSum(float v, float* scratch) {
#pragma unroll
    for (int o = 16; o; o >>= 1) v += __shfl_down_sync(0xffffffffu, v, o);
    int w = threadIdx.x >> 5, l = threadIdx.x & 31;
    __syncthreads();
    if (l == 0) scratch[w] = v;
    __syncthreads();
    if (w == 0) {
        float t = scratch[l];   // exactly 32 warps
#pragma unroll
        for (int o = 16; o; o >>= 1) t += __shfl_down_sync(0xffffffffu, t, o);
        if (l == 0) scratch[0] = t;
    }
    __syncthreads();
    return scratch[0];
}

// fused 2-way block reduction
__device__ __forceinline__ void blockReduce2(float& a, float& b, float* scratch) {
#pragma unroll
    for (int o = 16; o; o >>= 1) {
        a += __shfl_down_sync(0xffffffffu, a, o);
        b += __shfl_down_sync(0xffffffffu, b, o);
    }
    int w = threadIdx.x >> 5, l = threadIdx.x & 31;
    __syncthreads();
    if (l == 0) { scratch[w] = a; scratch[32 + w] = b; }
    __syncthreads();
    if (w == 0) {
        float ta = scratch[l], tb = scratch[32 + l];
#pragma unroll
        for (int o = 16; o; o >>= 1) {
            ta += __shfl_down_sync(0xffffffffu, ta, o);
            tb += __shfl_down_sync(0xffffffffu, tb, o);
        }
        if (l == 0) { scratch[0] = ta; scratch[32] = tb; }
    }
    __syncthreads();
    a = scratch[0]; b = scratch[32];
}

// ---- SMEM byte offsets ----
#define SM_KARR   0        // u64[4096] 32768   | counting: fArr f32[4096] (16KB)
#define SM_STK    32768    // uint4[4096] 65536 | counting: encArr 16KB + sPart 4KB
#define SM_DENSE  98304    // uint4[4096] 65536 | scatter: rLoc f[4096]
#define SM_FSTART 163840   // int[4097] 16388
#define SM_FMEAN  180228   // float[4096] 16384
#define SM_CNTA   196612   // int[512] 2048
#define SM_CNTB   198660   // int[512] 2048
#define SM_RED    200708   // float[64] 256
#define SM_WHO    200964   // u32[2]
#define SM_NB     200972   // int
#define SMEM_BYTES 200992

__global__ __launch_bounds__(NTHREADS, 1)
void fusedKernel(const float* __restrict__ yhat,
                 const float* __restrict__ ytar,
                 float* __restrict__ out) {
    extern __shared__ char sm[];
    u64*   kArr   = (u64*)(sm + SM_KARR);
    float* fArr   = (float*)(sm + SM_KARR);     // counting overlay
    uint4* stk    = (uint4*)(sm + SM_STK);
    u32*   encArr = (u32*)(sm + SM_STK);        // counting overlay (16KB)
    u32*   sPart  = (u32*)(sm + SM_STK + 16384);// counting overlay (4KB)
    uint4* dense  = (uint4*)(sm + SM_DENSE);
    float* rLoc   = (float*)(sm + SM_DENSE);    // scatter overlay (after merge)
    int*   fStart = (int*)(sm + SM_FSTART);
    float* fMean  = (float*)(sm + SM_FMEAN);
    int*   cntA   = (int*)(sm + SM_CNTA);
    int*   cntB   = (int*)(sm + SM_CNTB);
    float* red    = (float*)(sm + SM_RED);
    u32*   shWho  = (u32*)(sm + SM_WHO);
    int*   nbPtr  = (int*)(sm + SM_NB);

    const int tid  = threadIdx.x;
    const int lane = tid & 31;
    const int wrp  = tid >> 5;
    const int row  = blockIdx.x >> 6;
    const int ctaSlot = blockIdx.x & (NCTA_ROW - 1);
    const float* src = row ? ytar : yhat;

    // ============ Phase 1: dual-pipe rank-by-counting (128 CTAs) ============
    {
        float4 v = ((const float4*)src)[tid];
        ((float4*)fArr)[tid] = v;
        uint4 ev;
        ev.x = encodeVal(v.x); ev.y = encodeVal(v.y);
        ev.z = encodeVal(v.z); ev.w = encodeVal(v.w);
        ((uint4*)encArr)[tid] = ev;
    }
    // BCE slice for this CTA: 32 elements, warp 0. Issue LDGs now; latency
    // hides under the counting loop.
    float bx = 0.f, by = 0.f;
    if (wrp == 0) {
        int bi = blockIdx.x * 32 + lane;
        bx = yhat[bi];
        by = ytar[bi];
    }
    __syncthreads();

    {
        // lane = target, warp = value segment (256 values). First 128 values
        // compared as float (fma pipe), last 128 as encoded u32 (alu pipe).
        const int seg = wrp & 15;
        const int g   = wrp >> 4;
        const int ii  = ctaSlot * SLICE + g * 32 + lane;
        const float vi = fArr[ii];
        const u32   ei = encArr[ii];
        const float4* fq = (const float4*)(fArr + seg * 256);
        const uint4*  uq = (const uint4*)(encArr + seg * 256);
        float cf = 0.f;
        u32   ci = 0;
#pragma unroll 16
        for (int t = 0; t < 32; ++t) {
            float4 f = fq[t];           // values [seg*256, +128)
            uint4  u = uq[t + 32];      // values [seg*256+128, +128)
            cmpAccF(cf, f.x, vi); cmpAccU(ci, u.x, ei);
            cmpAccF(cf, f.y, vi); cmpAccU(ci, u.y, ei);
            cmpAccF(cf, f.z, vi); cmpAccU(ci, u.z, ei);
            cmpAccF(cf, f.w, vi); cmpAccU(ci, u.w, ei);
        }
        sPart[wrp * 32 + lane] = ci + (u32)cf;
    }

    // BCE partial: warp 0 computes, warp-reduces, writes g_part (fixed order
    // -> deterministic final sum).
    if (wrp == 0) {
        float b = fmaxf(bx, 0.f) + log1pf(expf(-fabsf(bx))) - bx * by;
#pragma unroll
        for (int o = 16; o; o >>= 1) b += __shfl_down_sync(0xffffffffu, b, o);
        if (lane == 0) g_part[blockIdx.x] = b;
    }
    __syncthreads();

    if (tid < SLICE) {
        int g = tid >> 5, ln = tid & 31;
        u32 pos = 0;
#pragma unroll
        for (int s = 0; s < 16; ++s)
            pos += sPart[(g * 16 + s) * 32 + ln];
        // pos = # strictly greater; ties get distinct slots via global ticket
        const int i = ctaSlot * SLICE + tid;
        const u32 en = encArr[i];
        u32 tick = atomicAdd(&g_tick[row][pos], 1u);
        g_keys[row][pos + tick] = ((u64)en << 32) | (u32)i;
    }

    // ============ gate 1: last CTA per row continues; rest exit ============
    __threadfence();
    __syncthreads();
    if (tid == 0) shWho[0] = atomicAdd(&g_cnt[row], 1);
    __syncthreads();
    if (shWho[0] != NCTA_ROW - 1) return;
    __threadfence();   // acquire other CTAs' g_keys writes

    // ============ Phase 2: PAV (1 CTA per row) ============
    {
        const u64* gk = g_keys[row];
#pragma unroll
        for (int m = 0; m < 4; m++) {
            int i = tid + m * NTHREADS;
            kArr[i] = gk[i];
            g_tick[row][i] = 0;          // reset own row's tickets (counting done)
        }
    }
    __syncthreads();

    // per-chunk PAV, CHUNK=8, all-float block state (exact: |sumW| < 2^24)
    if (tid < NCHUNK) {
        const int base = tid * CHUNK;
        float w  = (float)(N - base);            // w(i) = N - i, running
        float tS = decodeVal((u32)(kArr[base] >> 32));
        float tW = w, tC = 1.f;
        float tNum = tS - tW;
        int   tSt = base, sp = 0;
        for (int i = base + 1; i < base + CHUNK; ++i) {
            w -= 1.f;
            float s = decodeVal((u32)(kArr[i] >> 32));
            float cS = s, cW = w, cC = 1.f, cNum = s - w;
            int   cSt = i;
            while (tNum * cC < cNum * tC) {      // pool
                cS += tS; cW += tW; cC += tC; cSt = tSt;
                cNum = cS - cW;
                if (sp == 0) { tC = 0.f; break; }
                sp--;
                uint4 a = stk[base + sp];
                tS = __uint_as_float(a.x); tW = __uint_as_float(a.y);
                tC = __uint_as_float(a.z); tSt = (int)a.w;
                tNum = tS - tW;
            }
            if (tC > 0.f) { stk[base + sp] = packAtom(tS, tW, tC, tSt); sp++; }
            tS = cS; tW = cW; tC = cC; tSt = cSt; tNum = cNum;
        }
        stk[base + sp] = packAtom(tS, tW, tC, tSt); sp++;
        cntA[tid] = sp;
    }

    // ---- tree merge: 6 pairwise levels (512 -> 8 lists), then one serial
    //      8-list merge on thread 0 (no lane divergence). Identical result
    //      to the serial left-to-right PAV stream.
    uint4* finBuf;
    {
        uint4* srcB = stk;   uint4* dstB = dense;
        int*   sCnt = cntA;  int*   dCnt = cntB;
        int NL = NCHUNK, S = CHUNK;
        while (NL > 8) {
            __syncthreads();
            if (tid < (NL >> 1)) {
                const uint4* L = srcB + (2 * tid) * S;
                const uint4* R = srcB + (2 * tid + 1) * S;
                uint4* D = dstB + tid * (2 * S);
                int la = sCnt[2 * tid], lb = sCnt[2 * tid + 1];
                // copy left list except its last block (held in registers)
                for (int j = 0; j < la - 1; j++) D[j] = L[j];
                uint4 a = L[la - 1];
                float tS = __uint_as_float(a.x), tW = __uint_as_float(a.y);
                float tC = __uint_as_float(a.z);
                int   tSt = (int)a.w;
                float tNum = tS - tW;
                int sp = la - 1;
                for (int r = 0; r < lb; r++) {
                    uint4 b = R[r];
                    float cS = __uint_as_float(b.x), cW = __uint_as_float(b.y);
                    float cC = __uint_as_float(b.z);
                    int   cSt = (int)b.w;
                    float cNum = cS - cW;
                    while (tNum * cC < cNum * tC) {
                        cS += tS; cW += tW; cC += tC; cSt = tSt;
                        cNum = cS - cW;
                        if (sp == 0) { tC = 0.f; break; }
                        sp--;
                        uint4 p = D[sp];
                        tS = __uint_as_float(p.x); tW = __uint_as_float(p.y);
                        tC = __uint_as_float(p.z); tSt = (int)p.w;
                        tNum = tS - tW;
                    }
                    if (tC > 0.f) { D[sp++] = packAtom(tS, tW, tC, tSt); }
                    tS = cS; tW = cW; tC = cC; tSt = cSt; tNum = cNum;
                }
                D[sp++] = packAtom(tS, tW, tC, tSt);
                dCnt[tid] = sp;
            }
            uint4* tb = srcB; srcB = dstB; dstB = tb;
            int*   tc = sCnt; sCnt = dCnt; dCnt = tc;
            NL >>= 1; S <<= 1;
        }
        __syncthreads();
        if (tid == 0)
            *nbPtr = mergeLists(srcB, S, sCnt, 0, 8, dstB);
        finBuf = dstB;
    }
    __syncthreads();

    const int nb = *nbPtr;
    for (int b = tid; b < nb; b += NTHREADS) {
        uint4 a = finBuf[b];
        fStart[b] = (int)a.w;
        fMean[b]  = (__uint_as_float(a.x) - __uint_as_float(a.y))
                    / __uint_as_float(a.z);
    }
    if (tid == 0) fStart[nb] = N;
    __syncthreads();

    // ---- scatter + own-row moments (rLoc overlays dense; merge done) ----
    float sR = 0.f, sR2 = 0.f;
#pragma unroll
    for (int m = 0; m < 4; m++) {
        int i = tid + m * NTHREADS;
        u64 kk = kArr[i];
        float s = decodeVal((u32)(kk >> 32));
        int  id = (int)(kk & 0xFFFFFFFFu);
        int lo = 0, hi = nb - 1;
        while (lo < hi) {
            int mid = (lo + hi + 1) >> 1;
            if (fStart[mid] <= i) lo = mid; else hi = mid - 1;
        }
        float r = s - fMean[lo] - 2048.5f;     // shift is Spearman-invariant
        g_rank[row][id] = r;
        rLoc[id] = r;
        sR  += r;
        sR2 += r * r;
    }
    blockReduce2(sR, sR2, red);
    if (tid == 0) {
        g_sum[row]   = sR;
        g_sumsq[row] = sR2;
    }

    // ============ gate 2: second of the two row CTAs finishes ============
    __threadfence();
    __syncthreads();
    if (tid == 0) shWho[1] = atomicAdd(&g_cnt2, 1);
    __syncthreads();
    if (shWho[1] != 1) return;
    __threadfence();   // acquire other row's ranks + partials

    {
        const float* other = g_rank[1 - row];
        float cr = 0.f;
#pragma unroll
        for (int m = 0; m < 4; m++) {
            int i = tid + m * NTHREADS;
            cr += other[i] * rLoc[i];
        }
        float bp = (tid < 2 * NCTA_ROW) ? g_part[tid] : 0.f;
        blockReduce2(cr, bp, red);
        if (tid == 0) {
            float invN = 1.0f / (float)N;
            float mp = g_sum[0] * invN, mt = g_sum[1] * invN;
            float varP = g_sumsq[0] - (float)N * mp * mp;
            float varT = g_sumsq[1] - (float)N * mt * mt;
            float cov  = cr - (float)N * mp * mt;
            float sp   = cov * rsqrtf(varP * varT);
            out[0] = (1.0f - sp) + bp * invN;
            g_cnt[0] = 0; g_cnt[1] = 0; g_cnt2 = 0;   // reset for graph replay
        }
    }
}

extern "C" void kernel_launch(void* const* d_in, const int* in_sizes, int n_in,
                              void* d_out, int out_size) {
    const float* yhat = (const float*)d_in[0];
    const float* ytar = (const float*)d_in[1];
    float* out = (float*)d_out;
    cudaFuncSetAttribute(fusedKernel,
                         cudaFuncAttributeMaxDynamicSharedMemorySize, SMEM_BYTES);
    fusedKernel<<<2 * NCTA_ROW, NTHREADS, SMEM_BYTES>>>(yhat, ytar, out);
}